// round 1
// baseline (speedup 1.0000x reference)
#include <cuda_runtime.h>

// Problem constants
#define D_MODEL 1024
#define D_FF    4096
#define NEXP    8
#define NTOK    4096   // 4 * 1024 tokens

// Scratch (device globals: allocation-free, graph-capture safe)
__device__ float g_H[(size_t)NTOK * D_FF];   // hidden activations, indexed by token id
__device__ int   g_tok[NEXP * NTOK];          // per-expert token lists
__device__ int   g_cnt[NEXP];                 // per-expert token counts
__device__ float g_gate[NTOK];                // top-1 gate per token

// ---------------------------------------------------------------------------
// Init: zero the per-expert counters
// ---------------------------------------------------------------------------
__global__ void init_kernel() {
    if (threadIdx.x < NEXP) g_cnt[threadIdx.x] = 0;
}

// ---------------------------------------------------------------------------
// Router: one block (256 threads) per token.
//  - stage x row in smem
//  - warp e computes logit for expert e
//  - thread 0: argmax (first-max, matching jnp.argmax), softmax gate,
//    append token to expert list
// ---------------------------------------------------------------------------
__global__ void router_kernel(const float* __restrict__ x,
                              const float* __restrict__ rW,   // [D_MODEL, NEXP]
                              const float* __restrict__ rb) { // [NEXP]
    __shared__ float xs[D_MODEL];
    __shared__ float logits[NEXP];
    const int token = blockIdx.x;

    // 256 threads * float4 = 1024 floats
    const float4* xr  = (const float4*)(x + (size_t)token * D_MODEL);
    ((float4*)xs)[threadIdx.x] = xr[threadIdx.x];
    __syncthreads();

    const int e    = threadIdx.x >> 5;
    const int lane = threadIdx.x & 31;
    float s = 0.f;
    #pragma unroll 8
    for (int d = lane; d < D_MODEL; d += 32)
        s += xs[d] * rW[d * NEXP + e];
    #pragma unroll
    for (int o = 16; o > 0; o >>= 1) s += __shfl_down_sync(0xffffffffu, s, o);
    if (lane == 0) logits[e] = s + rb[e];
    __syncthreads();

    if (threadIdx.x == 0) {
        float mx = logits[0]; int am = 0;
        #pragma unroll
        for (int i = 1; i < NEXP; i++)
            if (logits[i] > mx) { mx = logits[i]; am = i; }   // strict > keeps first max
        float sum = 0.f;
        #pragma unroll
        for (int i = 0; i < NEXP; i++) sum += expf(logits[i] - mx);
        const float gate = 1.0f / sum;   // softmax prob of the argmax expert

        const int pos = atomicAdd(&g_cnt[am], 1);
        g_tok[am * NTOK + pos] = token;
        g_gate[token] = gate;
    }
}

// ---------------------------------------------------------------------------
// Grouped gather-GEMM.
//   C[tok, 0..N) = post( gather_A[tok, 0..K) @ B_e[K, N] + bias_e )
// Tile: BM=128 x BN=64 x BK=16, 256 threads, per-thread 8x4 register tile.
// MODE_A: 0 -> A param (x), 1 -> A = g_H
// MODE_C: 0 -> C param,     1 -> C = g_H
// RELU / GATE control the epilogue.
// ---------------------------------------------------------------------------
#define BM 128
#define BN 64
#define BK 16

template<bool A_IS_H, bool C_IS_H, bool RELU, bool GATE>
__global__ __launch_bounds__(256, 4)
void moe_gemm(const float* __restrict__ Ap,    // [NTOK, K] (token-id indexed)
              const float* __restrict__ B,     // [NEXP, K, N]
              const float* __restrict__ bias,  // [NEXP, N]
              float* __restrict__ Cp,          // [NTOK, N] (token-id indexed)
              int K, int N) {
    const int e   = blockIdx.z;
    const int cnt = g_cnt[e];
    const int m0  = blockIdx.y * BM;
    if (m0 >= cnt) return;                  // early-exit padding tiles
    const int n0  = blockIdx.x * BN;

    const float* __restrict__ A = A_IS_H ? g_H : Ap;
    float* __restrict__       C = C_IS_H ? g_H : Cp;

    __shared__ float As[BK][BM];
    __shared__ float Bs[BK][BN];

    const int tid  = threadIdx.x;

    // --- A load mapping: row = tid&127, col4 = tid>>7 then +2 (2 float4/thread)
    const int arow = tid & 127;
    const int ac4  = tid >> 7;
    const int rclamp = min(m0 + arow, cnt - 1);
    const int tokA = g_tok[e * NTOK + rclamp];
    const float* Arow = A + (size_t)tokA * K;

    // --- B load mapping: k = tid>>4, n4 = tid&15 (1 float4/thread)
    const int bk  = tid >> 4;
    const int bn4 = tid & 15;
    const float* Bexp = B + (size_t)e * K * N;

    // --- compute mapping: 16x16 thread grid, 8 rows x 4 cols each
    const int ty = tid >> 4;    // rows ty*8 .. ty*8+7
    const int tx = tid & 15;    // cols tx*4 .. tx*4+3

    float acc[8][4];
    #pragma unroll
    for (int i = 0; i < 8; i++)
        #pragma unroll
        for (int j = 0; j < 4; j++) acc[i][j] = 0.f;

    for (int k0 = 0; k0 < K; k0 += BK) {
        // stage A (transposed: As[k][m]) — conflict-free STS (arow distinct mod 32)
        #pragma unroll
        for (int t = 0; t < 2; t++) {
            const int c4 = ac4 + 2 * t;
            const float4 v = *(const float4*)(Arow + k0 + c4 * 4);
            As[c4 * 4 + 0][arow] = v.x;
            As[c4 * 4 + 1][arow] = v.y;
            As[c4 * 4 + 2][arow] = v.z;
            As[c4 * 4 + 3][arow] = v.w;
        }
        // stage B (row-major)
        *(float4*)&Bs[bk][bn4 * 4] =
            *(const float4*)(Bexp + (size_t)(k0 + bk) * N + n0 + bn4 * 4);
        __syncthreads();

        #pragma unroll
        for (int kk = 0; kk < BK; kk++) {
            const float4 a0 = *(const float4*)&As[kk][ty * 8];
            const float4 a1 = *(const float4*)&As[kk][ty * 8 + 4];
            const float4 bv = *(const float4*)&Bs[kk][tx * 4];
            const float a[8]  = {a0.x, a0.y, a0.z, a0.w, a1.x, a1.y, a1.z, a1.w};
            const float bb[4] = {bv.x, bv.y, bv.z, bv.w};
            #pragma unroll
            for (int i = 0; i < 8; i++)
                #pragma unroll
                for (int j = 0; j < 4; j++)
                    acc[i][j] = fmaf(a[i], bb[j], acc[i][j]);
        }
        __syncthreads();
    }

    // epilogue
    const float4 b4 = *(const float4*)(bias + (size_t)e * N + n0 + tx * 4);
    #pragma unroll
    for (int i = 0; i < 8; i++) {
        const int row = m0 + ty * 8 + i;
        if (row < cnt) {
            const int tok = g_tok[e * NTOK + row];
            float4 o;
            o.x = acc[i][0] + b4.x;
            o.y = acc[i][1] + b4.y;
            o.z = acc[i][2] + b4.z;
            o.w = acc[i][3] + b4.w;
            if (RELU) {
                o.x = fmaxf(o.x, 0.f); o.y = fmaxf(o.y, 0.f);
                o.z = fmaxf(o.z, 0.f); o.w = fmaxf(o.w, 0.f);
            }
            if (GATE) {
                const float g = g_gate[tok];
                o.x *= g; o.y *= g; o.z *= g; o.w *= g;
            }
            *(float4*)(C + (size_t)tok * N + n0 + tx * 4) = o;
        }
    }
}

// ---------------------------------------------------------------------------
// kernel_launch: init -> router -> GEMM1 (relu) -> GEMM2 (gate)
// All on the default stream; fully graph-capturable, allocation-free.
// ---------------------------------------------------------------------------
extern "C" void kernel_launch(void* const* d_in, const int* in_sizes, int n_in,
                              void* d_out, int out_size) {
    const float* x   = (const float*)d_in[0];  // [4,1024,1024]
    const float* rW  = (const float*)d_in[1];  // [1024,8]
    const float* rb  = (const float*)d_in[2];  // [8]
    const float* W1  = (const float*)d_in[3];  // [8,1024,4096]
    const float* b1  = (const float*)d_in[4];  // [8,4096]
    const float* W2  = (const float*)d_in[5];  // [8,4096,1024]
    const float* b2  = (const float*)d_in[6];  // [8,1024]
    float* out = (float*)d_out;                // [4,1024,1024]

    init_kernel<<<1, 32>>>();
    router_kernel<<<NTOK, 256>>>(x, rW, rb);

    // GEMM1: H = relu(x_gathered @ W1_e + b1_e), K=1024, N=4096
    {
        dim3 grid(D_FF / BN, NTOK / BM, NEXP);   // 64 x 32 x 8 (early-exit on padding)
        moe_gemm<false, true, true, false><<<grid, 256>>>(x, W1, b1, nullptr,
                                                          D_MODEL, D_FF);
    }
    // GEMM2: out = gate * (H_gathered @ W2_e + b2_e), K=4096, N=1024
    {
        dim3 grid(D_MODEL / BN, NTOK / BM, NEXP); // 16 x 32 x 8
        moe_gemm<true, false, false, true><<<grid, 256>>>(nullptr, W2, b2, out,
                                                          D_FF, D_MODEL);
    }
}

// round 2
// speedup vs baseline: 1.0010x; 1.0010x over previous
#include <cuda_runtime.h>

// Problem constants
#define D_MODEL 1024
#define D_FF    4096
#define NEXP    8
#define NTOK    4096   // 4 * 1024 tokens

// Scratch (device globals: allocation-free, graph-capture safe)
__device__ float g_H[(size_t)NTOK * D_FF];   // hidden activations, indexed by token id
__device__ int   g_tok[NEXP * NTOK];          // per-expert token lists
__device__ int   g_cnt[NEXP];                 // per-expert token counts
__device__ float g_gate[NTOK];                // top-1 gate per token

// ---------------------------------------------------------------------------
// Init: zero the per-expert counters
// ---------------------------------------------------------------------------
__global__ void init_kernel() {
    if (threadIdx.x < NEXP) g_cnt[threadIdx.x] = 0;
}

// ---------------------------------------------------------------------------
// Router: one block (256 threads) per token.
//  - stage x row in smem
//  - warp e computes logit for expert e
//  - thread 0: argmax (first-max, matching jnp.argmax), softmax gate,
//    append token to expert list
// ---------------------------------------------------------------------------
__global__ void router_kernel(const float* __restrict__ x,
                              const float* __restrict__ rW,   // [D_MODEL, NEXP]
                              const float* __restrict__ rb) { // [NEXP]
    __shared__ float xs[D_MODEL];
    __shared__ float logits[NEXP];
    const int token = blockIdx.x;

    // 256 threads * float4 = 1024 floats
    const float4* xr  = (const float4*)(x + (size_t)token * D_MODEL);
    ((float4*)xs)[threadIdx.x] = xr[threadIdx.x];
    __syncthreads();

    const int e    = threadIdx.x >> 5;
    const int lane = threadIdx.x & 31;
    float s = 0.f;
    #pragma unroll 8
    for (int d = lane; d < D_MODEL; d += 32)
        s += xs[d] * rW[d * NEXP + e];
    #pragma unroll
    for (int o = 16; o > 0; o >>= 1) s += __shfl_down_sync(0xffffffffu, s, o);
    if (lane == 0) logits[e] = s + rb[e];
    __syncthreads();

    if (threadIdx.x == 0) {
        float mx = logits[0]; int am = 0;
        #pragma unroll
        for (int i = 1; i < NEXP; i++)
            if (logits[i] > mx) { mx = logits[i]; am = i; }   // strict > keeps first max
        float sum = 0.f;
        #pragma unroll
        for (int i = 0; i < NEXP; i++) sum += expf(logits[i] - mx);
        const float gate = 1.0f / sum;   // softmax prob of the argmax expert

        const int pos = atomicAdd(&g_cnt[am], 1);
        g_tok[am * NTOK + pos] = token;
        g_gate[token] = gate;
    }
}

// ---------------------------------------------------------------------------
// Grouped gather-GEMM.
//   C[tok, 0..N) = post( gather_A[tok, 0..K) @ B_e[K, N] + bias_e )
// Tile: BM=128 x BN=64 x BK=16, 256 threads, per-thread 8x4 register tile.
// MODE_A: 0 -> A param (x), 1 -> A = g_H
// MODE_C: 0 -> C param,     1 -> C = g_H
// RELU / GATE control the epilogue.
// ---------------------------------------------------------------------------
#define BM 128
#define BN 64
#define BK 16

template<bool A_IS_H, bool C_IS_H, bool RELU, bool GATE>
__global__ __launch_bounds__(256, 4)
void moe_gemm(const float* __restrict__ Ap,    // [NTOK, K] (token-id indexed)
              const float* __restrict__ B,     // [NEXP, K, N]
              const float* __restrict__ bias,  // [NEXP, N]
              float* __restrict__ Cp,          // [NTOK, N] (token-id indexed)
              int K, int N) {
    const int e   = blockIdx.z;
    const int cnt = g_cnt[e];
    const int m0  = blockIdx.y * BM;
    if (m0 >= cnt) return;                  // early-exit padding tiles
    const int n0  = blockIdx.x * BN;

    const float* __restrict__ A = A_IS_H ? g_H : Ap;
    float* __restrict__       C = C_IS_H ? g_H : Cp;

    __shared__ float As[BK][BM];
    __shared__ float Bs[BK][BN];

    const int tid  = threadIdx.x;

    // --- A load mapping: row = tid&127, col4 = tid>>7 then +2 (2 float4/thread)
    const int arow = tid & 127;
    const int ac4  = tid >> 7;
    const int rclamp = min(m0 + arow, cnt - 1);
    const int tokA = g_tok[e * NTOK + rclamp];
    const float* Arow = A + (size_t)tokA * K;

    // --- B load mapping: k = tid>>4, n4 = tid&15 (1 float4/thread)
    const int bk  = tid >> 4;
    const int bn4 = tid & 15;
    const float* Bexp = B + (size_t)e * K * N;

    // --- compute mapping: 16x16 thread grid, 8 rows x 4 cols each
    const int ty = tid >> 4;    // rows ty*8 .. ty*8+7
    const int tx = tid & 15;    // cols tx*4 .. tx*4+3

    float acc[8][4];
    #pragma unroll
    for (int i = 0; i < 8; i++)
        #pragma unroll
        for (int j = 0; j < 4; j++) acc[i][j] = 0.f;

    for (int k0 = 0; k0 < K; k0 += BK) {
        // stage A (transposed: As[k][m]) — conflict-free STS (arow distinct mod 32)
        #pragma unroll
        for (int t = 0; t < 2; t++) {
            const int c4 = ac4 + 2 * t;
            const float4 v = *(const float4*)(Arow + k0 + c4 * 4);
            As[c4 * 4 + 0][arow] = v.x;
            As[c4 * 4 + 1][arow] = v.y;
            As[c4 * 4 + 2][arow] = v.z;
            As[c4 * 4 + 3][arow] = v.w;
        }
        // stage B (row-major)
        *(float4*)&Bs[bk][bn4 * 4] =
            *(const float4*)(Bexp + (size_t)(k0 + bk) * N + n0 + bn4 * 4);
        __syncthreads();

        #pragma unroll
        for (int kk = 0; kk < BK; kk++) {
            const float4 a0 = *(const float4*)&As[kk][ty * 8];
            const float4 a1 = *(const float4*)&As[kk][ty * 8 + 4];
            const float4 bv = *(const float4*)&Bs[kk][tx * 4];
            const float a[8]  = {a0.x, a0.y, a0.z, a0.w, a1.x, a1.y, a1.z, a1.w};
            const float bb[4] = {bv.x, bv.y, bv.z, bv.w};
            #pragma unroll
            for (int i = 0; i < 8; i++)
                #pragma unroll
                for (int j = 0; j < 4; j++)
                    acc[i][j] = fmaf(a[i], bb[j], acc[i][j]);
        }
        __syncthreads();
    }

    // epilogue
    const float4 b4 = *(const float4*)(bias + (size_t)e * N + n0 + tx * 4);
    #pragma unroll
    for (int i = 0; i < 8; i++) {
        const int row = m0 + ty * 8 + i;
        if (row < cnt) {
            const int tok = g_tok[e * NTOK + row];
            float4 o;
            o.x = acc[i][0] + b4.x;
            o.y = acc[i][1] + b4.y;
            o.z = acc[i][2] + b4.z;
            o.w = acc[i][3] + b4.w;
            if (RELU) {
                o.x = fmaxf(o.x, 0.f); o.y = fmaxf(o.y, 0.f);
                o.z = fmaxf(o.z, 0.f); o.w = fmaxf(o.w, 0.f);
            }
            if (GATE) {
                const float g = g_gate[tok];
                o.x *= g; o.y *= g; o.z *= g; o.w *= g;
            }
            *(float4*)(C + (size_t)tok * N + n0 + tx * 4) = o;
        }
    }
}

// ---------------------------------------------------------------------------
// kernel_launch: init -> router -> GEMM1 (relu) -> GEMM2 (gate)
// All on the default stream; fully graph-capturable, allocation-free.
// ---------------------------------------------------------------------------
extern "C" void kernel_launch(void* const* d_in, const int* in_sizes, int n_in,
                              void* d_out, int out_size) {
    const float* x   = (const float*)d_in[0];  // [4,1024,1024]
    const float* rW  = (const float*)d_in[1];  // [1024,8]
    const float* rb  = (const float*)d_in[2];  // [8]
    const float* W1  = (const float*)d_in[3];  // [8,1024,4096]
    const float* b1  = (const float*)d_in[4];  // [8,4096]
    const float* W2  = (const float*)d_in[5];  // [8,4096,1024]
    const float* b2  = (const float*)d_in[6];  // [8,1024]
    float* out = (float*)d_out;                // [4,1024,1024]

    init_kernel<<<1, 32>>>();
    router_kernel<<<NTOK, 256>>>(x, rW, rb);

    // GEMM1: H = relu(x_gathered @ W1_e + b1_e), K=1024, N=4096
    {
        dim3 grid(D_FF / BN, NTOK / BM, NEXP);   // 64 x 32 x 8 (early-exit on padding)
        moe_gemm<false, true, true, false><<<grid, 256>>>(x, W1, b1, nullptr,
                                                          D_MODEL, D_FF);
    }
    // GEMM2: out = gate * (H_gathered @ W2_e + b2_e), K=4096, N=1024
    {
        dim3 grid(D_MODEL / BN, NTOK / BM, NEXP); // 16 x 32 x 8
        moe_gemm<true, false, false, true><<<grid, 256>>>(nullptr, W2, b2, out,
                                                          D_FF, D_MODEL);
    }
}

// round 4
// speedup vs baseline: 2.8324x; 2.8297x over previous
#include <cuda_runtime.h>
#include <cuda_bf16.h>
#include <cstdint>

#define D_MODEL 1024
#define D_FF    4096
#define NEXP    8
#define NTOK    4096
#define MAXTILES 40
#define NROWPAD (MAXTILES * 128)   // 5120 padded rows

// ---------------------------------------------------------------------------
// Device-global scratch (allocation-free, graph-capture safe)
// ---------------------------------------------------------------------------
__device__ int   g_tok[NEXP * NTOK];
__device__ int   g_cnt[NEXP];
__device__ float g_gate[NTOK];
__device__ int   g_poff[NEXP];
__device__ int   g_tile_expert[MAXTILES];
__device__ int   g_row2tok[NROWPAD];

__device__ __align__(16) __nv_bfloat16 g_xhi[(size_t)NROWPAD * D_MODEL];
__device__ __align__(16) __nv_bfloat16 g_xlo[(size_t)NROWPAD * D_MODEL];
__device__ __align__(16) __nv_bfloat16 g_W1hi[(size_t)NEXP * D_FF * D_MODEL]; // [E][N][K]
__device__ __align__(16) __nv_bfloat16 g_W1lo[(size_t)NEXP * D_FF * D_MODEL];
__device__ __align__(16) __nv_bfloat16 g_W2hi[(size_t)NEXP * D_MODEL * D_FF]; // [E][N][K]
__device__ __align__(16) __nv_bfloat16 g_W2lo[(size_t)NEXP * D_MODEL * D_FF];
__device__ __align__(16) __nv_bfloat16 g_Hhi[(size_t)NROWPAD * D_FF];
__device__ __align__(16) __nv_bfloat16 g_Hlo[(size_t)NROWPAD * D_FF];

// ---------------------------------------------------------------------------
// helpers
// ---------------------------------------------------------------------------
__device__ __forceinline__ uint32_t smem_u32(const void* p) {
    uint32_t a;
    asm("{ .reg .u64 t; cvta.to.shared.u64 t, %1; cvt.u32.u64 %0, t; }"
        : "=r"(a) : "l"(p));
    return a;
}
__device__ __forceinline__ void split2(float v, __nv_bfloat16& h, __nv_bfloat16& l) {
    h = __float2bfloat16(v);
    l = __float2bfloat16(v - __bfloat162float(h));
}
// swizzled byte offset into a [rows][32 bf16] (64B/row) smem tile
__device__ __forceinline__ uint32_t sw_off(int r, int kelem) {
    const int chunk = kelem >> 3;                       // 16B chunk within row
    return (uint32_t)(r * 64 + (((chunk ^ ((r >> 1) & 3)) & 3) << 4)
                      + ((kelem & 7) << 1));
}
__device__ __forceinline__ void ldsm4(uint32_t* r, uint32_t addr) {
    asm volatile("ldmatrix.sync.aligned.m8n8.x4.shared.b16 {%0,%1,%2,%3}, [%4];"
                 : "=r"(r[0]), "=r"(r[1]), "=r"(r[2]), "=r"(r[3]) : "r"(addr));
}
__device__ __forceinline__ void mma16816(float* d, const uint32_t* a,
                                         const uint32_t* b) {
    asm volatile("mma.sync.aligned.m16n8k16.row.col.f32.bf16.bf16.f32 "
                 "{%0,%1,%2,%3}, {%4,%5,%6,%7}, {%8,%9}, {%0,%1,%2,%3};"
                 : "+f"(d[0]), "+f"(d[1]), "+f"(d[2]), "+f"(d[3])
                 : "r"(a[0]), "r"(a[1]), "r"(a[2]), "r"(a[3]),
                   "r"(b[0]), "r"(b[1]));
}
#define CP_ASYNC16(dst, src) \
    asm volatile("cp.async.cg.shared.global [%0], [%1], 16;" :: "r"(dst), "l"(src))
#define CP_COMMIT()  asm volatile("cp.async.commit_group;" ::: "memory")
#define CP_WAIT1()   asm volatile("cp.async.wait_group 1;" ::: "memory")

// ---------------------------------------------------------------------------
// init / router / build / convert (round-2, verified compiling + correct)
// ---------------------------------------------------------------------------
__global__ void init_kernel() {
    if (threadIdx.x < NEXP) g_cnt[threadIdx.x] = 0;
}

__global__ void router_kernel(const float* __restrict__ x,
                              const float* __restrict__ rW,
                              const float* __restrict__ rb) {
    __shared__ float xs[D_MODEL];
    __shared__ float logits[NEXP];
    const int token = blockIdx.x;
    ((float4*)xs)[threadIdx.x] = ((const float4*)(x + (size_t)token * D_MODEL))[threadIdx.x];
    __syncthreads();
    const int e = threadIdx.x >> 5, lane = threadIdx.x & 31;
    float s = 0.f;
    #pragma unroll 8
    for (int d = lane; d < D_MODEL; d += 32) s += xs[d] * rW[d * NEXP + e];
    #pragma unroll
    for (int o = 16; o > 0; o >>= 1) s += __shfl_down_sync(0xffffffffu, s, o);
    if (lane == 0) logits[e] = s + rb[e];
    __syncthreads();
    if (threadIdx.x == 0) {
        float mx = logits[0]; int am = 0;
        #pragma unroll
        for (int i = 1; i < NEXP; i++)
            if (logits[i] > mx) { mx = logits[i]; am = i; }
        float sum = 0.f;
        #pragma unroll
        for (int i = 0; i < NEXP; i++) sum += expf(logits[i] - mx);
        const int pos = atomicAdd(&g_cnt[am], 1);
        g_tok[am * NTOK + pos] = token;
        g_gate[token] = 1.0f / sum;
    }
}

__global__ void build_kernel() {
    if (threadIdx.x != 0) return;
    int off = 0;
    for (int e = 0; e < NEXP; e++) {
        g_poff[e] = off;
        int tiles = (g_cnt[e] + 127) >> 7;
        for (int t = 0; t < tiles; t++) g_tile_expert[(off >> 7) + t] = e;
        off += tiles << 7;
    }
    for (int t = off >> 7; t < MAXTILES; t++) g_tile_expert[t] = -1;
}

__global__ void convert_x_kernel(const float* __restrict__ x) {
    const int row = blockIdx.x;
    const int e = g_tile_expert[row >> 7];
    int tok = -1;
    if (e >= 0) {
        const int local = row - g_poff[e];
        if (local < g_cnt[e]) tok = g_tok[e * NTOK + local];
    }
    if (threadIdx.x == 0) g_row2tok[row] = tok;
    const int d0 = threadIdx.x * 4;
    float4 v = make_float4(0.f, 0.f, 0.f, 0.f);
    if (tok >= 0) v = *(const float4*)(x + (size_t)tok * D_MODEL + d0);
    union { __nv_bfloat16 b[4]; uint2 u; } H, L;
    split2(v.x, H.b[0], L.b[0]); split2(v.y, H.b[1], L.b[1]);
    split2(v.z, H.b[2], L.b[2]); split2(v.w, H.b[3], L.b[3]);
    *(uint2*)(g_xhi + (size_t)row * D_MODEL + d0) = H.u;
    *(uint2*)(g_xlo + (size_t)row * D_MODEL + d0) = L.u;
}

template<int WHICH>  // 1 -> W1, 2 -> W2
__global__ void convert_w_kernel(const float* __restrict__ W, int K, int N) {
    __shared__ float t[32][33];
    const int e = blockIdx.z, n0 = blockIdx.x * 32, k0 = blockIdx.y * 32;
    const int tx = threadIdx.x, ty = threadIdx.y;
    __nv_bfloat16* Whi = (WHICH == 1) ? g_W1hi : g_W2hi;
    __nv_bfloat16* Wlo = (WHICH == 1) ? g_W1lo : g_W2lo;
    #pragma unroll
    for (int i = 0; i < 4; i++)
        t[ty + 8 * i][tx] = W[((size_t)e * K + k0 + ty + 8 * i) * N + n0 + tx];
    __syncthreads();
    #pragma unroll
    for (int i = 0; i < 4; i++) {
        const float v = t[tx][ty + 8 * i];
        __nv_bfloat16 h, l; split2(v, h, l);
        const size_t o = ((size_t)e * N + n0 + ty + 8 * i) * K + k0 + tx;
        Whi[o] = h; Wlo[o] = l;
    }
}

// ---------------------------------------------------------------------------
// bf16 mma.sync grouped GEMM: 128x256 tile, BK=32, 3-stage cp.async pipeline.
//   3-term split: Ahi*Bhi + Alo*Bhi + Ahi*Blo
// smem stage: Ahi 8K | Alo 8K | Bhi 16K | Blo 16K = 48K; 3 stages = 144K
// ---------------------------------------------------------------------------
#define STAGE_BYTES 49152
#define SMEM_GEMM   (3 * STAGE_BYTES)

template<int R>
__device__ __forceinline__ void stage_cp(const __nv_bfloat16* __restrict__ src,
                                         int ld, uint32_t dst, int tid) {
    #pragma unroll
    for (int u = tid; u < R * 4; u += 256) {
        const int r = u >> 2, c = u & 3;
        const uint32_t d = dst + r * 64 + (((c ^ ((r >> 1) & 3)) & 3) << 4);
        CP_ASYNC16(d, src + (size_t)r * ld + c * 8);
    }
}

template<int KTOT, int NTOT, bool IS_G1>
__global__ __launch_bounds__(256, 1)
void moe_gemm_mma(const float* __restrict__ bias, float* __restrict__ outp) {
    const int e = g_tile_expert[blockIdx.y];
    if (e < 0) return;
    const int m0 = blockIdx.y * 128;
    const int n0 = blockIdx.x * 256;

    extern __shared__ char smem[];
    const uint32_t sb = smem_u32(smem);
    const int tid = threadIdx.x, lane = tid & 31, wid = tid >> 5;
    const int wm = (wid & 3) * 32;        // warp m-base (4 warps in m)
    const int wn = (wid >> 2) * 128;      // warp n-base (2 warps in n)

    const __nv_bfloat16* Ahi = (IS_G1 ? g_xhi : g_Hhi) + (size_t)m0 * KTOT;
    const __nv_bfloat16* Alo = (IS_G1 ? g_xlo : g_Hlo) + (size_t)m0 * KTOT;
    const __nv_bfloat16* Bhi = (IS_G1 ? g_W1hi : g_W2hi) + ((size_t)e * NTOT + n0) * KTOT;
    const __nv_bfloat16* Blo = (IS_G1 ? g_W1lo : g_W2lo) + ((size_t)e * NTOT + n0) * KTOT;

    // ldmatrix lane addressing
    const int a_r  = wm + (lane & 15);            // + mt*16
    const int a_k  = (lane >> 4) * 8;             // + ks*16
    const int b_r  = wn + (lane & 7) + ((lane >> 4) << 3);   // + nt*16
    const int b_k  = ((lane >> 3) & 1) * 8;       // + ks*16

    float acc[128];
    #pragma unroll
    for (int i = 0; i < 128; i++) acc[i] = 0.f;

    const int NSTAGE = KTOT / 32;

    auto issue = [&](int s, int buf) {
        const uint32_t base = sb + buf * STAGE_BYTES;
        const int k0 = s * 32;
        stage_cp<128>(Ahi + k0, KTOT, base,         tid);
        stage_cp<128>(Alo + k0, KTOT, base + 8192,  tid);
        stage_cp<256>(Bhi + k0, KTOT, base + 16384, tid);
        stage_cp<256>(Blo + k0, KTOT, base + 32768, tid);
    };

    issue(0, 0); CP_COMMIT();
    issue(1, 1); CP_COMMIT();

    int buf = 0;
    #pragma unroll 1
    for (int s = 0; s < NSTAGE; s++) {
        CP_WAIT1();
        __syncthreads();
        const int nbuf = (buf + 2 >= 3) ? buf - 1 : buf + 2;
        if (s + 2 < NSTAGE) issue(s + 2, nbuf);
        CP_COMMIT();

        const uint32_t Ah = sb + buf * STAGE_BYTES;
        const uint32_t Al = Ah + 8192;
        const uint32_t Bh = Ah + 16384;
        const uint32_t Bl = Ah + 32768;
        #pragma unroll
        for (int ks = 0; ks < 2; ks++) {
            uint32_t ahi[2][4], alo[2][4];
            #pragma unroll
            for (int mt = 0; mt < 2; mt++) {
                const uint32_t off = sw_off(a_r + mt * 16, ks * 16 + a_k);
                ldsm4(ahi[mt], Ah + off);
                ldsm4(alo[mt], Al + off);
            }
            #pragma unroll
            for (int nt = 0; nt < 8; nt++) {
                const uint32_t bo = sw_off(b_r + nt * 16, ks * 16 + b_k);
                uint32_t bhi[4], blo[4];
                ldsm4(bhi, Bh + bo);
                ldsm4(blo, Bl + bo);
                #pragma unroll
                for (int mt = 0; mt < 2; mt++) {
                    float* d0 = acc + (mt * 16 + 2 * nt) * 4;
                    float* d1 = acc + (mt * 16 + 2 * nt + 1) * 4;
                    mma16816(d0, ahi[mt], bhi);
                    mma16816(d0, alo[mt], bhi);
                    mma16816(d0, ahi[mt], blo);
                    mma16816(d1, ahi[mt], bhi + 2);
                    mma16816(d1, alo[mt], bhi + 2);
                    mma16816(d1, ahi[mt], blo + 2);
                }
            }
        }
        buf = (buf + 1 == 3) ? 0 : buf + 1;
    }

    // ---- epilogue ----
    const int gq = lane >> 2, tq = lane & 3;
    #pragma unroll
    for (int mt = 0; mt < 2; mt++) {
        #pragma unroll
        for (int half = 0; half < 2; half++) {   // row, row+8
            const int row = m0 + wm + mt * 16 + gq + half * 8;
            int tok = 0; float gate = 0.f;
            if (!IS_G1) {
                tok = g_row2tok[row];
                if (tok >= 0) gate = g_gate[tok];
            }
            #pragma unroll
            for (int nt = 0; nt < 16; nt++) {
                const int col = n0 + wn + nt * 8 + tq * 2;
                const float* d = acc + (mt * 16 + nt) * 4 + half * 2;
                if (IS_G1) {
                    float v0 = d[0] + bias[e * D_FF + col];
                    float v1 = d[1] + bias[e * D_FF + col + 1];
                    v0 = fmaxf(v0, 0.f); v1 = fmaxf(v1, 0.f);
                    __nv_bfloat16 h0, l0, h1, l1;
                    split2(v0, h0, l0); split2(v1, h1, l1);
                    __nv_bfloat162 H; H.x = h0; H.y = h1;
                    __nv_bfloat162 L; L.x = l0; L.y = l1;
                    *(__nv_bfloat162*)(g_Hhi + (size_t)row * D_FF + col) = H;
                    *(__nv_bfloat162*)(g_Hlo + (size_t)row * D_FF + col) = L;
                } else if (tok >= 0) {
                    float2 o;
                    o.x = (d[0] + bias[e * D_MODEL + col])     * gate;
                    o.y = (d[1] + bias[e * D_MODEL + col + 1]) * gate;
                    *(float2*)(outp + (size_t)tok * D_MODEL + col) = o;
                }
            }
        }
    }
}

// ---------------------------------------------------------------------------
// kernel_launch
// ---------------------------------------------------------------------------
extern "C" void kernel_launch(void* const* d_in, const int* in_sizes, int n_in,
                              void* d_out, int out_size) {
    const float* x  = (const float*)d_in[0];
    const float* rW = (const float*)d_in[1];
    const float* rb = (const float*)d_in[2];
    const float* W1 = (const float*)d_in[3];
    const float* b1 = (const float*)d_in[4];
    const float* W2 = (const float*)d_in[5];
    const float* b2 = (const float*)d_in[6];
    float* out = (float*)d_out;

    // idempotent; called every time (no static guards). Errors ignored —
    // once set during the correctness call, the attribute persists.
    cudaFuncSetAttribute(moe_gemm_mma<D_MODEL, D_FF, true>,
                         cudaFuncAttributeMaxDynamicSharedMemorySize, SMEM_GEMM);
    cudaFuncSetAttribute(moe_gemm_mma<D_FF, D_MODEL, false>,
                         cudaFuncAttributeMaxDynamicSharedMemorySize, SMEM_GEMM);

    init_kernel<<<1, 32>>>();
    router_kernel<<<NTOK, 256>>>(x, rW, rb);
    build_kernel<<<1, 32>>>();
    convert_x_kernel<<<NROWPAD, 256>>>(x);
    {   // W1: K=1024, N=4096
        dim3 grid(D_FF / 32, D_MODEL / 32, NEXP);
        convert_w_kernel<1><<<grid, dim3(32, 8)>>>(W1, D_MODEL, D_FF);
    }
    {   // W2: K=4096, N=1024
        dim3 grid(D_MODEL / 32, D_FF / 32, NEXP);
        convert_w_kernel<2><<<grid, dim3(32, 8)>>>(W2, D_FF, D_MODEL);
    }
    {   // GEMM1: H = relu(Xp @ W1t^T + b1), K=1024, N=4096
        dim3 grid(D_FF / 256, MAXTILES);
        moe_gemm_mma<D_MODEL, D_FF, true><<<grid, 256, SMEM_GEMM>>>(b1, nullptr);
    }
    {   // GEMM2: out = gate * (H @ W2t^T + b2), K=4096, N=1024
        dim3 grid(D_MODEL / 256, MAXTILES);
        moe_gemm_mma<D_FF, D_MODEL, false><<<grid, 256, SMEM_GEMM>>>(b2, out);
    }
}

// round 6
// speedup vs baseline: 3.9531x; 1.3957x over previous
#include <cuda_runtime.h>
#include <cuda_fp16.h>
#include <cstdint>

#define D_MODEL 1024
#define D_FF    4096
#define NEXP    8
#define NTOK    4096
#define MAXTILES 40
#define NROWPAD (MAXTILES * 128)   // 5120 padded rows

// ---------------------------------------------------------------------------
// Device-global scratch (allocation-free, graph-capture safe)
// ---------------------------------------------------------------------------
__device__ int   g_tok[NEXP * NTOK];
__device__ int   g_cnt[NEXP];
__device__ float g_gate[NTOK];
__device__ int   g_poff[NEXP];
__device__ int   g_tile_expert[MAXTILES];
__device__ int   g_row2tok[NROWPAD];

__device__ __align__(16) __half g_xhi[(size_t)NROWPAD * D_MODEL];
__device__ __align__(16) __half g_xlo[(size_t)NROWPAD * D_MODEL];
__device__ __align__(16) __half g_W1h[(size_t)NEXP * D_FF * D_MODEL];  // [E][N][K]
__device__ __align__(16) __half g_W2h[(size_t)NEXP * D_MODEL * D_FF];  // [E][N][K]
__device__ __align__(16) __half g_Hhi[(size_t)NROWPAD * D_FF];
__device__ __align__(16) __half g_Hlo[(size_t)NROWPAD * D_FF];

// ---------------------------------------------------------------------------
// helpers
// ---------------------------------------------------------------------------
__device__ __forceinline__ uint32_t smem_u32(const void* p) {
    uint32_t a;
    asm("{ .reg .u64 t; cvta.to.shared.u64 t, %1; cvt.u32.u64 %0, t; }"
        : "=r"(a) : "l"(p));
    return a;
}
__device__ __forceinline__ void split2(float v, __half& h, __half& l) {
    h = __float2half(v);
    l = __float2half(v - __half2float(h));
}
// swizzled byte offset into a [rows][32 halfs] (64B/row) smem tile
__device__ __forceinline__ uint32_t sw_off(int r, int kelem) {
    const int chunk = kelem >> 3;                       // 16B chunk within row
    return (uint32_t)(r * 64 + (((chunk ^ ((r >> 1) & 3)) & 3) << 4)
                      + ((kelem & 7) << 1));
}
__device__ __forceinline__ void ldsm4(uint32_t* r, uint32_t addr) {
    asm volatile("ldmatrix.sync.aligned.m8n8.x4.shared.b16 {%0,%1,%2,%3}, [%4];"
                 : "=r"(r[0]), "=r"(r[1]), "=r"(r[2]), "=r"(r[3]) : "r"(addr));
}
__device__ __forceinline__ void mma16816(float* d, const uint32_t* a,
                                         const uint32_t* b) {
    asm volatile("mma.sync.aligned.m16n8k16.row.col.f32.f16.f16.f32 "
                 "{%0,%1,%2,%3}, {%4,%5,%6,%7}, {%8,%9}, {%0,%1,%2,%3};"
                 : "+f"(d[0]), "+f"(d[1]), "+f"(d[2]), "+f"(d[3])
                 : "r"(a[0]), "r"(a[1]), "r"(a[2]), "r"(a[3]),
                   "r"(b[0]), "r"(b[1]));
}
#define CP_ASYNC16(dst, src) \
    asm volatile("cp.async.cg.shared.global [%0], [%1], 16;" :: "r"(dst), "l"(src))
#define CP_COMMIT()  asm volatile("cp.async.commit_group;" ::: "memory")
#define CP_WAIT1()   asm volatile("cp.async.wait_group 1;" ::: "memory")

// ---------------------------------------------------------------------------
// init / router / build  (unchanged, verified)
// ---------------------------------------------------------------------------
__global__ void init_kernel() {
    if (threadIdx.x < NEXP) g_cnt[threadIdx.x] = 0;
}

__global__ void router_kernel(const float* __restrict__ x,
                              const float* __restrict__ rW,
                              const float* __restrict__ rb) {
    __shared__ float xs[D_MODEL];
    __shared__ float logits[NEXP];
    const int token = blockIdx.x;
    ((float4*)xs)[threadIdx.x] = ((const float4*)(x + (size_t)token * D_MODEL))[threadIdx.x];
    __syncthreads();
    const int e = threadIdx.x >> 5, lane = threadIdx.x & 31;
    float s = 0.f;
    #pragma unroll 8
    for (int d = lane; d < D_MODEL; d += 32) s += xs[d] * rW[d * NEXP + e];
    #pragma unroll
    for (int o = 16; o > 0; o >>= 1) s += __shfl_down_sync(0xffffffffu, s, o);
    if (lane == 0) logits[e] = s + rb[e];
    __syncthreads();
    if (threadIdx.x == 0) {
        float mx = logits[0]; int am = 0;
        #pragma unroll
        for (int i = 1; i < NEXP; i++)
            if (logits[i] > mx) { mx = logits[i]; am = i; }
        float sum = 0.f;
        #pragma unroll
        for (int i = 0; i < NEXP; i++) sum += expf(logits[i] - mx);
        const int pos = atomicAdd(&g_cnt[am], 1);
        g_tok[am * NTOK + pos] = token;
        g_gate[token] = 1.0f / sum;
    }
}

__global__ void build_kernel() {
    if (threadIdx.x != 0) return;
    int off = 0;
    for (int e = 0; e < NEXP; e++) {
        g_poff[e] = off;
        int tiles = (g_cnt[e] + 127) >> 7;
        for (int t = 0; t < tiles; t++) g_tile_expert[(off >> 7) + t] = e;
        off += tiles << 7;
    }
    for (int t = off >> 7; t < MAXTILES; t++) g_tile_expert[t] = -1;
}

// ---------------------------------------------------------------------------
// convert_x: gather token rows into packed/padded order, split to fp16 hi/lo
// ---------------------------------------------------------------------------
__global__ void convert_x_kernel(const float* __restrict__ x) {
    const int row = blockIdx.x;
    const int e = g_tile_expert[row >> 7];
    int tok = -1;
    if (e >= 0) {
        const int local = row - g_poff[e];
        if (local < g_cnt[e]) tok = g_tok[e * NTOK + local];
    }
    if (threadIdx.x == 0) g_row2tok[row] = tok;
    const int d0 = threadIdx.x * 4;
    float4 v = make_float4(0.f, 0.f, 0.f, 0.f);
    if (tok >= 0) v = *(const float4*)(x + (size_t)tok * D_MODEL + d0);
    union { __half b[4]; uint2 u; } H, L;
    split2(v.x, H.b[0], L.b[0]); split2(v.y, H.b[1], L.b[1]);
    split2(v.z, H.b[2], L.b[2]); split2(v.w, H.b[3], L.b[3]);
    *(uint2*)(g_xhi + (size_t)row * D_MODEL + d0) = H.u;
    *(uint2*)(g_xlo + (size_t)row * D_MODEL + d0) = L.u;
}

// ---------------------------------------------------------------------------
// transpose_w: [E][K][N] fp32 -> [E][N][K] fp16 (hi only)
// 64x64 tile, float4 loads, 16B packed-half stores.
// ---------------------------------------------------------------------------
template<int WHICH>  // 1 -> W1, 2 -> W2
__global__ __launch_bounds__(256)
void transpose_w_kernel(const float* __restrict__ W, int K, int N) {
    __shared__ float t[64][65];
    const int e = blockIdx.z, k0 = blockIdx.x * 64, n0 = blockIdx.y * 64;
    const int tid = threadIdx.x;
    __half* __restrict__ Wh = (WHICH == 1) ? g_W1h : g_W2h;

    const int c4 = tid & 15, r0 = tid >> 4;
    #pragma unroll
    for (int i = 0; i < 4; i++) {
        const int kr = r0 + i * 16;
        const float4 v = *(const float4*)(W + ((size_t)e * K + k0 + kr) * N + n0 + c4 * 4);
        t[kr][c4 * 4 + 0] = v.x; t[kr][c4 * 4 + 1] = v.y;
        t[kr][c4 * 4 + 2] = v.z; t[kr][c4 * 4 + 3] = v.w;
    }
    __syncthreads();
    #pragma unroll
    for (int i = 0; i < 2; i++) {
        const int u = tid + 256 * i;
        const int n = u >> 3, ch = u & 7;
        union { __half h[8]; uint4 q; } P;
        #pragma unroll
        for (int j = 0; j < 8; j++) P.h[j] = __float2half(t[ch * 8 + j][n]);
        *(uint4*)(Wh + ((size_t)e * N + n0 + n) * K + k0 + ch * 8) = P.q;
    }
}

// ---------------------------------------------------------------------------
// fp16 mma grouped GEMM: 128x256 tile, BK=32, 3-stage cp.async pipeline.
//   2-term split: Ahi*Wh + Alo*Wh   (W fp16-quantized, A exact hi+lo)
// stage: Ahi 8K | Alo 8K | B 16K = 32K; 3 stages = 96K
// Warps: 4(m) x 2(n), warp tile 32m x 128n  (identical to round-4 layout)
// ---------------------------------------------------------------------------
#define STAGE_BYTES 32768
#define SMEM_GEMM   (3 * STAGE_BYTES)

template<int R>
__device__ __forceinline__ void stage_cp(const __half* __restrict__ src,
                                         int ld, uint32_t dst, int tid) {
    #pragma unroll
    for (int u = tid; u < R * 4; u += 256) {
        const int r = u >> 2, c = u & 3;
        const uint32_t d = dst + r * 64 + (((c ^ ((r >> 1) & 3)) & 3) << 4);
        CP_ASYNC16(d, src + (size_t)r * ld + c * 8);
    }
}

template<int KTOT, int NTOT, bool IS_G1>
__global__ __launch_bounds__(256, 1)
void moe_gemm_mma(const float* __restrict__ bias, float* __restrict__ outp) {
    const int e = g_tile_expert[blockIdx.y];
    if (e < 0) return;
    const int m0 = blockIdx.y * 128;
    const int n0 = blockIdx.x * 256;

    extern __shared__ char smem[];
    const uint32_t sb = smem_u32(smem);
    const int tid = threadIdx.x, lane = tid & 31, wid = tid >> 5;
    const int wm = (wid & 3) * 32;        // warp m-base (4 warps in m)
    const int wn = (wid >> 2) * 128;      // warp n-base (2 warps in n)

    const __half* Ahi = (IS_G1 ? g_xhi : g_Hhi) + (size_t)m0 * KTOT;
    const __half* Alo = (IS_G1 ? g_xlo : g_Hlo) + (size_t)m0 * KTOT;
    const __half* Bw  = (IS_G1 ? g_W1h : g_W2h) + ((size_t)e * NTOT + n0) * KTOT;

    // ldmatrix lane addressing (round-4 verified)
    const int a_r = wm + (lane & 15);                       // + mt*16
    const int a_k = (lane >> 4) * 8;                        // + ks*16
    const int b_r = wn + (lane & 7) + ((lane >> 4) << 3);   // + nt*16
    const int b_k = ((lane >> 3) & 1) * 8;                  // + ks*16

    float acc[128];
    #pragma unroll
    for (int i = 0; i < 128; i++) acc[i] = 0.f;

    const int NSTAGE = KTOT / 32;

    auto issue = [&](int s, int buf) {
        const uint32_t base = sb + buf * STAGE_BYTES;
        const int k0 = s * 32;
        stage_cp<128>(Ahi + k0, KTOT, base,         tid);
        stage_cp<128>(Alo + k0, KTOT, base + 8192,  tid);
        stage_cp<256>(Bw  + k0, KTOT, base + 16384, tid);
    };

    issue(0, 0); CP_COMMIT();
    issue(1, 1); CP_COMMIT();

    int buf = 0;
    #pragma unroll 1
    for (int s = 0; s < NSTAGE; s++) {
        CP_WAIT1();
        __syncthreads();
        const int nbuf = (buf + 2 >= 3) ? buf - 1 : buf + 2;
        if (s + 2 < NSTAGE) issue(s + 2, nbuf);
        CP_COMMIT();

        const uint32_t Ah = sb + buf * STAGE_BYTES;
        const uint32_t Al = Ah + 8192;
        const uint32_t Bh = Ah + 16384;
        #pragma unroll
        for (int ks = 0; ks < 2; ks++) {
            uint32_t ahi[2][4], alo[2][4];
            #pragma unroll
            for (int mt = 0; mt < 2; mt++) {
                const uint32_t off = sw_off(a_r + mt * 16, ks * 16 + a_k);
                ldsm4(ahi[mt], Ah + off);
                ldsm4(alo[mt], Al + off);
            }
            #pragma unroll
            for (int nt = 0; nt < 8; nt++) {
                const uint32_t bo = sw_off(b_r + nt * 16, ks * 16 + b_k);
                uint32_t b[4];
                ldsm4(b, Bh + bo);
                #pragma unroll
                for (int mt = 0; mt < 2; mt++) {
                    float* d0 = acc + (mt * 16 + 2 * nt) * 4;
                    float* d1 = acc + (mt * 16 + 2 * nt + 1) * 4;
                    mma16816(d0, ahi[mt], b);
                    mma16816(d0, alo[mt], b);
                    mma16816(d1, ahi[mt], b + 2);
                    mma16816(d1, alo[mt], b + 2);
                }
            }
        }
        buf = (buf + 1 == 3) ? 0 : buf + 1;
    }

    // ---- epilogue (round-4 mapping, fp16 splits) ----
    const int gq = lane >> 2, tq = lane & 3;
    #pragma unroll
    for (int mt = 0; mt < 2; mt++) {
        #pragma unroll
        for (int half = 0; half < 2; half++) {   // row, row+8
            const int row = m0 + wm + mt * 16 + gq + half * 8;
            int tok = 0; float gate = 0.f;
            if (!IS_G1) {
                tok = g_row2tok[row];
                if (tok >= 0) gate = g_gate[tok];
            }
            #pragma unroll
            for (int nt = 0; nt < 16; nt++) {
                const int col = n0 + wn + nt * 8 + tq * 2;
                const float* d = acc + (mt * 16 + nt) * 4 + half * 2;
                if (IS_G1) {
                    float v0 = d[0] + bias[e * D_FF + col];
                    float v1 = d[1] + bias[e * D_FF + col + 1];
                    v0 = fmaxf(v0, 0.f); v1 = fmaxf(v1, 0.f);
                    __half h0, l0, h1, l1;
                    split2(v0, h0, l0); split2(v1, h1, l1);
                    __half2 H; H.x = h0; H.y = h1;
                    __half2 L; L.x = l0; L.y = l1;
                    *(__half2*)(g_Hhi + (size_t)row * D_FF + col) = H;
                    *(__half2*)(g_Hlo + (size_t)row * D_FF + col) = L;
                } else if (tok >= 0) {
                    float2 o;
                    o.x = (d[0] + bias[e * D_MODEL + col])     * gate;
                    o.y = (d[1] + bias[e * D_MODEL + col + 1]) * gate;
                    *(float2*)(outp + (size_t)tok * D_MODEL + col) = o;
                }
            }
        }
    }
}

// ---------------------------------------------------------------------------
// kernel_launch
// ---------------------------------------------------------------------------
extern "C" void kernel_launch(void* const* d_in, const int* in_sizes, int n_in,
                              void* d_out, int out_size) {
    const float* x  = (const float*)d_in[0];
    const float* rW = (const float*)d_in[1];
    const float* rb = (const float*)d_in[2];
    const float* W1 = (const float*)d_in[3];
    const float* b1 = (const float*)d_in[4];
    const float* W2 = (const float*)d_in[5];
    const float* b2 = (const float*)d_in[6];
    float* out = (float*)d_out;

    cudaFuncSetAttribute(moe_gemm_mma<D_MODEL, D_FF, true>,
                         cudaFuncAttributeMaxDynamicSharedMemorySize, SMEM_GEMM);
    cudaFuncSetAttribute(moe_gemm_mma<D_FF, D_MODEL, false>,
                         cudaFuncAttributeMaxDynamicSharedMemorySize, SMEM_GEMM);

    init_kernel<<<1, 32>>>();
    router_kernel<<<NTOK, 256>>>(x, rW, rb);
    build_kernel<<<1, 32>>>();
    convert_x_kernel<<<NROWPAD, 256>>>(x);
    {   // W1: K=1024, N=4096 -> [E][4096][1024]
        dim3 grid(D_MODEL / 64, D_FF / 64, NEXP);
        transpose_w_kernel<1><<<grid, 256>>>(W1, D_MODEL, D_FF);
    }
    {   // W2: K=4096, N=1024 -> [E][1024][4096]
        dim3 grid(D_FF / 64, D_MODEL / 64, NEXP);
        transpose_w_kernel<2><<<grid, 256>>>(W2, D_FF, D_MODEL);
    }
    {   // GEMM1: H = relu(Xp @ W1t^T + b1), K=1024, N=4096
        dim3 grid(D_FF / 256, MAXTILES);
        moe_gemm_mma<D_MODEL, D_FF, true><<<grid, 256, SMEM_GEMM>>>(b1, nullptr);
    }
    {   // GEMM2: out = gate * (H @ W2t^T + b2), K=4096, N=1024
        dim3 grid(D_MODEL / 256, MAXTILES);
        moe_gemm_mma<D_FF, D_MODEL, false><<<grid, 256, SMEM_GEMM>>>(b2, out);
    }
}

// round 7
// speedup vs baseline: 5.4801x; 1.3863x over previous
#include <cuda_runtime.h>
#include <cuda_fp16.h>
#include <cstdint>

#define D_MODEL 1024
#define D_FF    4096
#define NEXP    8
#define NTOK    4096
#define MAXTILES 40
#define NROWPAD (MAXTILES * 128)   // 5120 padded rows

// ---------------------------------------------------------------------------
// Device-global scratch (allocation-free, graph-capture safe)
// ---------------------------------------------------------------------------
__device__ int   g_tok[NEXP * NTOK];
__device__ int   g_cnt[NEXP];
__device__ float g_gate[NTOK];
__device__ int   g_poff[NEXP];
__device__ int   g_tile_expert[MAXTILES];
__device__ int   g_row2tok[NROWPAD];

__device__ __align__(16) __half g_xh[(size_t)NROWPAD * D_MODEL];
__device__ __align__(16) __half g_W1h[(size_t)NEXP * D_FF * D_MODEL];  // [E][N][K]
__device__ __align__(16) __half g_W2h[(size_t)NEXP * D_MODEL * D_FF];  // [E][N][K]
__device__ __align__(16) __half g_Hh[(size_t)NROWPAD * D_FF];

// ---------------------------------------------------------------------------
// helpers
// ---------------------------------------------------------------------------
__device__ __forceinline__ uint32_t smem_u32(const void* p) {
    uint32_t a;
    asm("{ .reg .u64 t; cvta.to.shared.u64 t, %1; cvt.u32.u64 %0, t; }"
        : "=r"(a) : "l"(p));
    return a;
}
// swizzled byte offset into a [rows][32 halfs] (64B/row) smem tile
__device__ __forceinline__ uint32_t sw_off(int r, int kelem) {
    const int chunk = kelem >> 3;                       // 16B chunk within row
    return (uint32_t)(r * 64 + (((chunk ^ ((r >> 1) & 3)) & 3) << 4)
                      + ((kelem & 7) << 1));
}
__device__ __forceinline__ void ldsm4(uint32_t* r, uint32_t addr) {
    asm volatile("ldmatrix.sync.aligned.m8n8.x4.shared.b16 {%0,%1,%2,%3}, [%4];"
                 : "=r"(r[0]), "=r"(r[1]), "=r"(r[2]), "=r"(r[3]) : "r"(addr));
}
__device__ __forceinline__ void mma16816(float* d, const uint32_t* a,
                                         const uint32_t* b) {
    asm volatile("mma.sync.aligned.m16n8k16.row.col.f32.f16.f16.f32 "
                 "{%0,%1,%2,%3}, {%4,%5,%6,%7}, {%8,%9}, {%0,%1,%2,%3};"
                 : "+f"(d[0]), "+f"(d[1]), "+f"(d[2]), "+f"(d[3])
                 : "r"(a[0]), "r"(a[1]), "r"(a[2]), "r"(a[3]),
                   "r"(b[0]), "r"(b[1]));
}
#define CP_ASYNC16(dst, src) \
    asm volatile("cp.async.cg.shared.global [%0], [%1], 16;" :: "r"(dst), "l"(src))
#define CP_COMMIT()  asm volatile("cp.async.commit_group;" ::: "memory")
#define CP_WAIT1()   asm volatile("cp.async.wait_group 1;" ::: "memory")

// ---------------------------------------------------------------------------
// init / router / build  (unchanged, verified)
// ---------------------------------------------------------------------------
__global__ void init_kernel() {
    if (threadIdx.x < NEXP) g_cnt[threadIdx.x] = 0;
}

__global__ void router_kernel(const float* __restrict__ x,
                              const float* __restrict__ rW,
                              const float* __restrict__ rb) {
    __shared__ float xs[D_MODEL];
    __shared__ float logits[NEXP];
    const int token = blockIdx.x;
    ((float4*)xs)[threadIdx.x] = ((const float4*)(x + (size_t)token * D_MODEL))[threadIdx.x];
    __syncthreads();
    const int e = threadIdx.x >> 5, lane = threadIdx.x & 31;
    float s = 0.f;
    #pragma unroll 8
    for (int d = lane; d < D_MODEL; d += 32) s += xs[d] * rW[d * NEXP + e];
    #pragma unroll
    for (int o = 16; o > 0; o >>= 1) s += __shfl_down_sync(0xffffffffu, s, o);
    if (lane == 0) logits[e] = s + rb[e];
    __syncthreads();
    if (threadIdx.x == 0) {
        float mx = logits[0]; int am = 0;
        #pragma unroll
        for (int i = 1; i < NEXP; i++)
            if (logits[i] > mx) { mx = logits[i]; am = i; }
        float sum = 0.f;
        #pragma unroll
        for (int i = 0; i < NEXP; i++) sum += expf(logits[i] - mx);
        const int pos = atomicAdd(&g_cnt[am], 1);
        g_tok[am * NTOK + pos] = token;
        g_gate[token] = 1.0f / sum;
    }
}

__global__ void build_kernel() {
    if (threadIdx.x != 0) return;
    int off = 0;
    for (int e = 0; e < NEXP; e++) {
        g_poff[e] = off;
        int tiles = (g_cnt[e] + 127) >> 7;
        for (int t = 0; t < tiles; t++) g_tile_expert[(off >> 7) + t] = e;
        off += tiles << 7;
    }
    for (int t = off >> 7; t < MAXTILES; t++) g_tile_expert[t] = -1;
}

// ---------------------------------------------------------------------------
// convert_x: gather token rows into packed/padded order, fp16
// ---------------------------------------------------------------------------
__global__ void convert_x_kernel(const float* __restrict__ x) {
    const int row = blockIdx.x;
    const int e = g_tile_expert[row >> 7];
    int tok = -1;
    if (e >= 0) {
        const int local = row - g_poff[e];
        if (local < g_cnt[e]) tok = g_tok[e * NTOK + local];
    }
    if (threadIdx.x == 0) g_row2tok[row] = tok;
    const int d0 = threadIdx.x * 4;
    float4 v = make_float4(0.f, 0.f, 0.f, 0.f);
    if (tok >= 0) v = *(const float4*)(x + (size_t)tok * D_MODEL + d0);
    union { __half b[4]; uint2 u; } H;
    H.b[0] = __float2half(v.x); H.b[1] = __float2half(v.y);
    H.b[2] = __float2half(v.z); H.b[3] = __float2half(v.w);
    *(uint2*)(g_xh + (size_t)row * D_MODEL + d0) = H.u;
}

// ---------------------------------------------------------------------------
// transpose_w: [E][K][N] fp32 -> [E][N][K] fp16
// 64x64 tile, float4 loads, 16B packed-half stores.  (round-6 verified)
// ---------------------------------------------------------------------------
template<int WHICH>  // 1 -> W1, 2 -> W2
__global__ __launch_bounds__(256)
void transpose_w_kernel(const float* __restrict__ W, int K, int N) {
    __shared__ float t[64][65];
    const int e = blockIdx.z, k0 = blockIdx.x * 64, n0 = blockIdx.y * 64;
    const int tid = threadIdx.x;
    __half* __restrict__ Wh = (WHICH == 1) ? g_W1h : g_W2h;

    const int c4 = tid & 15, r0 = tid >> 4;
    #pragma unroll
    for (int i = 0; i < 4; i++) {
        const int kr = r0 + i * 16;
        const float4 v = *(const float4*)(W + ((size_t)e * K + k0 + kr) * N + n0 + c4 * 4);
        t[kr][c4 * 4 + 0] = v.x; t[kr][c4 * 4 + 1] = v.y;
        t[kr][c4 * 4 + 2] = v.z; t[kr][c4 * 4 + 3] = v.w;
    }
    __syncthreads();
    #pragma unroll
    for (int i = 0; i < 2; i++) {
        const int u = tid + 256 * i;
        const int n = u >> 3, ch = u & 7;
        union { __half h[8]; uint4 q; } P;
        #pragma unroll
        for (int j = 0; j < 8; j++) P.h[j] = __float2half(t[ch * 8 + j][n]);
        *(uint4*)(Wh + ((size_t)e * N + n0 + n) * K + k0 + ch * 8) = P.q;
    }
}

// ---------------------------------------------------------------------------
// fp16 mma grouped GEMM: 128x256 tile, BK=32, 3-stage cp.async pipeline.
//   Plain fp16 operands, fp32 accumulate.
// stage: A 8K | B 16K = 24K; 3 stages = 72K
// Warps: 4(m) x 2(n), warp tile 32m x 128n  (round-4/6 verified layout)
// ---------------------------------------------------------------------------
#define STAGE_BYTES 24576
#define SMEM_GEMM   (3 * STAGE_BYTES)

template<int R>
__device__ __forceinline__ void stage_cp(const __half* __restrict__ src,
                                         int ld, uint32_t dst, int tid) {
    #pragma unroll
    for (int u = tid; u < R * 4; u += 256) {
        const int r = u >> 2, c = u & 3;
        const uint32_t d = dst + r * 64 + (((c ^ ((r >> 1) & 3)) & 3) << 4);
        CP_ASYNC16(d, src + (size_t)r * ld + c * 8);
    }
}

template<int KTOT, int NTOT, bool IS_G1>
__global__ __launch_bounds__(256, 1)
void moe_gemm_mma(const float* __restrict__ bias, float* __restrict__ outp) {
    const int e = g_tile_expert[blockIdx.y];
    if (e < 0) return;
    const int m0 = blockIdx.y * 128;
    const int n0 = blockIdx.x * 256;

    extern __shared__ char smem[];
    const uint32_t sb = smem_u32(smem);
    const int tid = threadIdx.x, lane = tid & 31, wid = tid >> 5;
    const int wm = (wid & 3) * 32;        // warp m-base (4 warps in m)
    const int wn = (wid >> 2) * 128;      // warp n-base (2 warps in n)

    const __half* Ah = (IS_G1 ? g_xh : g_Hh) + (size_t)m0 * KTOT;
    const __half* Bw = (IS_G1 ? g_W1h : g_W2h) + ((size_t)e * NTOT + n0) * KTOT;

    // ldmatrix lane addressing (verified)
    const int a_r = wm + (lane & 15);                       // + mt*16
    const int a_k = (lane >> 4) * 8;                        // + ks*16
    const int b_r = wn + (lane & 7) + ((lane >> 4) << 3);   // + nt*16
    const int b_k = ((lane >> 3) & 1) * 8;                  // + ks*16

    float acc[128];
    #pragma unroll
    for (int i = 0; i < 128; i++) acc[i] = 0.f;

    const int NSTAGE = KTOT / 32;

    auto issue = [&](int s, int buf) {
        const uint32_t base = sb + buf * STAGE_BYTES;
        const int k0 = s * 32;
        stage_cp<128>(Ah + k0, KTOT, base,        tid);
        stage_cp<256>(Bw + k0, KTOT, base + 8192, tid);
    };

    issue(0, 0); CP_COMMIT();
    issue(1, 1); CP_COMMIT();

    int buf = 0;
    #pragma unroll 1
    for (int s = 0; s < NSTAGE; s++) {
        CP_WAIT1();
        __syncthreads();
        const int nbuf = (buf + 2 >= 3) ? buf - 1 : buf + 2;
        if (s + 2 < NSTAGE) issue(s + 2, nbuf);
        CP_COMMIT();

        const uint32_t As = sb + buf * STAGE_BYTES;
        const uint32_t Bs = As + 8192;
        #pragma unroll
        for (int ks = 0; ks < 2; ks++) {
            uint32_t a[2][4];
            #pragma unroll
            for (int mt = 0; mt < 2; mt++)
                ldsm4(a[mt], As + sw_off(a_r + mt * 16, ks * 16 + a_k));
            #pragma unroll
            for (int nt = 0; nt < 8; nt++) {
                uint32_t b[4];
                ldsm4(b, Bs + sw_off(b_r + nt * 16, ks * 16 + b_k));
                #pragma unroll
                for (int mt = 0; mt < 2; mt++) {
                    float* d0 = acc + (mt * 16 + 2 * nt) * 4;
                    float* d1 = acc + (mt * 16 + 2 * nt + 1) * 4;
                    mma16816(d0, a[mt], b);
                    mma16816(d1, a[mt], b + 2);
                }
            }
        }
        buf = (buf + 1 == 3) ? 0 : buf + 1;
    }

    // ---- epilogue (verified mapping) ----
    const int gq = lane >> 2, tq = lane & 3;
    #pragma unroll
    for (int mt = 0; mt < 2; mt++) {
        #pragma unroll
        for (int half = 0; half < 2; half++) {   // row, row+8
            const int row = m0 + wm + mt * 16 + gq + half * 8;
            int tok = 0; float gate = 0.f;
            if (!IS_G1) {
                tok = g_row2tok[row];
                if (tok >= 0) gate = g_gate[tok];
            }
            #pragma unroll
            for (int nt = 0; nt < 16; nt++) {
                const int col = n0 + wn + nt * 8 + tq * 2;
                const float* d = acc + (mt * 16 + nt) * 4 + half * 2;
                if (IS_G1) {
                    float v0 = d[0] + bias[e * D_FF + col];
                    float v1 = d[1] + bias[e * D_FF + col + 1];
                    v0 = fmaxf(v0, 0.f); v1 = fmaxf(v1, 0.f);
                    __half2 H;
                    H.x = __float2half(v0); H.y = __float2half(v1);
                    *(__half2*)(g_Hh + (size_t)row * D_FF + col) = H;
                } else if (tok >= 0) {
                    float2 o;
                    o.x = (d[0] + bias[e * D_MODEL + col])     * gate;
                    o.y = (d[1] + bias[e * D_MODEL + col + 1]) * gate;
                    *(float2*)(outp + (size_t)tok * D_MODEL + col) = o;
                }
            }
        }
    }
}

// ---------------------------------------------------------------------------
// kernel_launch
// ---------------------------------------------------------------------------
extern "C" void kernel_launch(void* const* d_in, const int* in_sizes, int n_in,
                              void* d_out, int out_size) {
    const float* x  = (const float*)d_in[0];
    const float* rW = (const float*)d_in[1];
    const float* rb = (const float*)d_in[2];
    const float* W1 = (const float*)d_in[3];
    const float* b1 = (const float*)d_in[4];
    const float* W2 = (const float*)d_in[5];
    const float* b2 = (const float*)d_in[6];
    float* out = (float*)d_out;

    cudaFuncSetAttribute(moe_gemm_mma<D_MODEL, D_FF, true>,
                         cudaFuncAttributeMaxDynamicSharedMemorySize, SMEM_GEMM);
    cudaFuncSetAttribute(moe_gemm_mma<D_FF, D_MODEL, false>,
                         cudaFuncAttributeMaxDynamicSharedMemorySize, SMEM_GEMM);

    init_kernel<<<1, 32>>>();
    router_kernel<<<NTOK, 256>>>(x, rW, rb);
    build_kernel<<<1, 32>>>();
    convert_x_kernel<<<NROWPAD, 256>>>(x);
    {   // W1: K=1024, N=4096 -> [E][4096][1024]
        dim3 grid(D_MODEL / 64, D_FF / 64, NEXP);
        transpose_w_kernel<1><<<grid, 256>>>(W1, D_MODEL, D_FF);
    }
    {   // W2: K=4096, N=1024 -> [E][1024][4096]
        dim3 grid(D_FF / 64, D_MODEL / 64, NEXP);
        transpose_w_kernel<2><<<grid, 256>>>(W2, D_FF, D_MODEL);
    }
    {   // GEMM1: H = relu(Xp @ W1t^T + b1), K=1024, N=4096
        dim3 grid(D_FF / 256, MAXTILES);
        moe_gemm_mma<D_MODEL, D_FF, true><<<grid, 256, SMEM_GEMM>>>(b1, nullptr);
    }
    {   // GEMM2: out = gate * (H @ W2t^T + b2), K=4096, N=1024
        dim3 grid(D_MODEL / 256, MAXTILES);
        moe_gemm_mma<D_FF, D_MODEL, false><<<grid, 256, SMEM_GEMM>>>(b2, out);
    }
}